// round 1
// baseline (speedup 1.0000x reference)
#include <cuda_runtime.h>
#include <cstdint>

#define NB 8
#define CC 64
#define HH 192
#define WW 192
#define HP 194
#define WP 194
#define NPIX (NB*HH*WW)      /* 294912 */
#define VOL  (NPIX*CC)       /* 18874368 */

// ---------------- scratch (static device globals; zero-initialized) ----------------
__device__ int8_t g_A1[NB*HP*WP*CC];     // quantized act 1, NHWC, zero-padded halo
__device__ int8_t g_A2[NB*HP*WP*CC];     // quantized act 2, NHWC, zero-padded halo
__device__ float  g_X1[VOL];             // conv1 output post-prelu, NHWC fp32
__device__ float  g_Y2[VOL];             // conv2 raw output, NHWC fp32
__device__ int8_t g_w1p[9*4*64*16];      // packed weights [tap][cg][cout][16 cin-bytes]
__device__ int8_t g_w2p[9*4*64*16];
__device__ float  g_S[2];                // combined conv scales (a_scale * w_scale)
__device__ double g_bn1s[CC], g_bn1q[CC], g_bn2s[CC], g_bn2q[CC];
__device__ float  g_c1s[CC], g_c1b[CC], g_c2s[CC], g_c2b[CC];

// ---------------- kernel 1: weight quantization + accumulator zeroing ----------------
__global__ void k_wquant(const float* __restrict__ w1, const float* __restrict__ w2,
                         const float* __restrict__ a1, const float* __restrict__ a2)
{
    int b = blockIdx.x, t = threadIdx.x;
    if (b == 2) {
        if (t < CC) { g_bn1s[t] = 0.0; g_bn1q[t] = 0.0; g_bn2s[t] = 0.0; g_bn2q[t] = 0.0; }
        return;
    }
    const float* w = b ? w2 : w1;
    int8_t* wp = b ? g_w2p : g_w1p;
    __shared__ float red[256];
    float m = 0.f;
    for (int i = t; i < 36864; i += 256) m = fmaxf(m, fabsf(w[i]));
    red[t] = m; __syncthreads();
    for (int s = 128; s; s >>= 1) { if (t < s) red[t] = fmaxf(red[t], red[t+s]); __syncthreads(); }
    float sw = red[0] / 127.0f;   // weight scale
    if (t == 0) g_S[b] = ((b ? a2[0] : a1[0]) / 127.0f) * sw;
    for (int i = t; i < 36864; i += 256) {
        float q = rintf(w[i] / sw);
        q = fminf(fmaxf(q, -127.f), 127.f);
        int o = i / 576, ci = (i / 9) % 64, tap = i % 9;
        wp[((tap*4 + (ci >> 4))*64 + o)*16 + (ci & 15)] = (int8_t)q;
    }
}

// ---------------- kernel 2: quantize identity, NCHW fp32 -> NHWC int8 (padded) -------
__global__ void k_quant1(const float* __restrict__ x, const float* __restrict__ a1p)
{
    __shared__ uchar4 sb[32][17];
    int w0 = blockIdx.x*32, h = blockIdx.y, n = blockIdx.z;
    int tx = threadIdx.x, ty = threadIdx.y;         // 32 x 8
    float al = a1p[0], sc = al / 127.0f;
    #pragma unroll
    for (int k = 0; k < 2; k++) {
        int cg = ty + 8*k;                           // 0..15
        union { int8_t b[4]; uchar4 v; } u;
        #pragma unroll
        for (int j = 0; j < 4; j++) {
            int c = cg*4 + j;
            float xv = x[((n*CC + c)*HH + h)*WW + w0 + tx];
            xv = fminf(fmaxf(xv, -al), al);
            u.b[j] = (int8_t)(int)rintf(xv / sc);
        }
        sb[tx][cg] = u.v;
    }
    __syncthreads();
    int tid = ty*32 + tx;
    #pragma unroll
    for (int k = 0; k < 2; k++) {
        int uu = tid + 256*k;                        // 0..511
        int p = uu >> 4, cg = uu & 15;
        *reinterpret_cast<uchar4*>(&g_A1[((n*HP + h+1)*WP + (w0+p+1))*64 + cg*4]) = sb[p][cg];
    }
}

// ---------------- conv engine: dp4a implicit 3x3 conv, exact int32 ------------------
template<bool FIRST>
__global__ void __launch_bounds__(256) k_conv(const float* __restrict__ pa_p)
{
    __shared__ int4  sA[3*66*4];     // 3 rows x 66 pixels x 64B
    __shared__ float sR[2][64];
    const int8_t* A  = FIRST ? g_A1  : g_A2;
    const int4*   W4 = (const int4*)(FIRST ? g_w1p : g_w2p);
    float* Xout      = FIRST ? g_X1  : g_Y2;
    double* bs       = FIRST ? g_bn1s : g_bn2s;
    double* bq       = FIRST ? g_bn1q : g_bn2q;

    int tx = threadIdx.x, ty = threadIdx.y;          // 64 x 4
    int tid = ty*64 + tx;
    int w0 = blockIdx.x*64, h = blockIdx.y, n = blockIdx.z;

    const int4* A4 = (const int4*)A;
    for (int u = tid; u < 792; u += 256) {
        int dh = u / 264, r = u % 264;
        sA[u] = A4[((n*HP + h + dh)*WP + w0)*4 + r];
    }
    if (tid < 64) { sR[0][tid] = 0.f; sR[1][tid] = 0.f; }
    __syncthreads();

    int acc[16];
    #pragma unroll
    for (int k = 0; k < 16; k++) acc[k] = 0;

    #pragma unroll 1
    for (int t = 0; t < 9; t++) {
        int dh = t/3, dw = t%3;
        const int4* ar = sA + (dh*66 + ty*16 + dw)*4;
        #pragma unroll
        for (int cg = 0; cg < 4; cg++) {
            int4 wv = __ldg(&W4[(t*4 + cg)*64 + tx]);
            #pragma unroll
            for (int k = 0; k < 16; k++) {
                int4 av = ar[k*4 + cg];
                acc[k] = __dp4a(av.x, wv.x, acc[k]);
                acc[k] = __dp4a(av.y, wv.y, acc[k]);
                acc[k] = __dp4a(av.z, wv.z, acc[k]);
                acc[k] = __dp4a(av.w, wv.w, acc[k]);
            }
        }
    }

    float S  = g_S[FIRST ? 0 : 1];
    float pa = FIRST ? pa_p[0] : 0.f;
    float s = 0.f, q = 0.f;
    int pixbase = (n*HH + h)*WW + w0 + ty*16;
    #pragma unroll
    for (int k = 0; k < 16; k++) {
        float y = S * (float)acc[k];
        if (FIRST) y = (y >= 0.f) ? y : pa * y;      // PReLU only after conv1
        Xout[(pixbase + k)*64 + tx] = y;
        s += y; q += y*y;
    }
    atomicAdd(&sR[0][tx], s);
    atomicAdd(&sR[1][tx], q);
    __syncthreads();
    if (tid < 64) {
        atomicAdd(&bs[tid], (double)sR[0][tid]);
        atomicAdd(&bq[tid], (double)sR[1][tid]);
    }
}

// ---------------- BN stats finalize -> per-channel scale/shift ----------------------
template<bool FIRST>
__global__ void k_stats(const float* __restrict__ gamma, const float* __restrict__ beta)
{
    int c = threadIdx.x;
    const double* bs = FIRST ? g_bn1s : g_bn2s;
    const double* bq = FIRST ? g_bn1q : g_bn2q;
    double invn = 1.0 / (double)NPIX;
    double mean = bs[c] * invn;
    double var  = bq[c] * invn - mean*mean;
    float scl = gamma[c] * rsqrtf((float)var + 1e-5f);
    if (FIRST) { g_c1s[c] = scl; g_c1b[c] = beta[c] - (float)mean * scl; }
    else       { g_c2s[c] = scl; g_c2b[c] = beta[c] - (float)mean * scl; }
}

// ---------------- fused BN1-apply + quant_act(alpha2) -> int8 NHWC padded ------------
__global__ void k_quant2(const float* __restrict__ a2p)
{
    int u = blockIdx.x*256 + threadIdx.x;           // over NPIX*16
    int p = u >> 4, cg = u & 15;
    float al = a2p[0], sc = al / 127.0f;
    float4 xv = *reinterpret_cast<const float4*>(&g_X1[p*64 + cg*4]);
    union { int8_t b[4]; uchar4 v; } r;
    const float* xf = (const float*)&xv;
    #pragma unroll
    for (int j = 0; j < 4; j++) {
        int c = cg*4 + j;
        float v = xf[j] * g_c1s[c] + g_c1b[c];
        v = fminf(fmaxf(v, -al), al);
        r.b[j] = (int8_t)(int)rintf(v / sc);
    }
    int n = p / (HH*WW), hw = p % (HH*WW), h = hw / WW, w = hw % WW;
    *reinterpret_cast<uchar4*>(&g_A2[((n*HP + h+1)*WP + (w+1))*64 + cg*4]) = r.v;
}

// ---------------- final: BN2-apply + NHWC->NCHW + residual + scalar tail -------------
__global__ void k_final(const float* __restrict__ idn, const float* __restrict__ shortcut,
                        float* __restrict__ out, const float* __restrict__ bits,
                        const float* __restrict__ f, const float* __restrict__ bout,
                        int out_size)
{
    __shared__ float sT[64][33];
    int w0 = blockIdx.x*32, h = blockIdx.y, n = blockIdx.z;
    int tx = threadIdx.x, ty = threadIdx.y;          // 32 x 8
    int tid = ty*32 + tx;
    int base = ((n*HH + h)*WW + w0)*64;
    #pragma unroll
    for (int k = 0; k < 8; k++) {
        int u = tid + 256*k;                         // 0..2047
        int c = u & 63, p = u >> 6;
        float y = g_Y2[base + u];
        sT[c][p] = y * g_c2s[c] + g_c2b[c];
    }
    __syncthreads();
    float sh = shortcut[0];
    #pragma unroll
    for (int k = 0; k < 8; k++) {
        int c = ty + 8*k;
        int o = ((n*CC + c)*HH + h)*WW + w0 + tx;
        out[o] = idn[o]*sh + sT[c][tx];
    }
    if (blockIdx.x == 0 && blockIdx.y == 0 && blockIdx.z == 0 && tid == 0 && out_size >= VOL + 3) {
        out[VOL]   = bits[0];
        out[VOL+1] = f[0];
        out[VOL+2] = bout[0];
    }
}

// ---------------- launch -------------------------------------------------------------
extern "C" void kernel_launch(void* const* d_in, const int* in_sizes, int n_in,
                              void* d_out, int out_size)
{
    (void)in_sizes; (void)n_in;
    const float* identity = (const float*)d_in[0];
    const float* bits     = (const float*)d_in[1];
    const float* f        = (const float*)d_in[2];
    const float* bits_out = (const float*)d_in[3];
    const float* w1       = (const float*)d_in[4];
    const float* w2       = (const float*)d_in[5];
    const float* alpha1   = (const float*)d_in[6];
    const float* alpha2   = (const float*)d_in[7];
    const float* gamma1   = (const float*)d_in[8];
    const float* beta1    = (const float*)d_in[9];
    const float* gamma2   = (const float*)d_in[10];
    const float* beta2    = (const float*)d_in[11];
    const float* prelu_a  = (const float*)d_in[12];
    const float* shortcut = (const float*)d_in[13];
    float* out = (float*)d_out;

    k_wquant<<<3, 256>>>(w1, w2, alpha1, alpha2);
    k_quant1<<<dim3(6,192,8), dim3(32,8)>>>(identity, alpha1);
    k_conv<true><<<dim3(3,192,8), dim3(64,4)>>>(prelu_a);
    k_stats<true><<<1, 64>>>(gamma1, beta1);
    k_quant2<<<(NPIX*16)/256, 256>>>(alpha2);
    k_conv<false><<<dim3(3,192,8), dim3(64,4)>>>(prelu_a);
    k_stats<false><<<1, 64>>>(gamma2, beta2);
    k_final<<<dim3(6,192,8), dim3(32,8)>>>(identity, shortcut, out, bits, f, bits_out, out_size);
}